// round 1
// baseline (speedup 1.0000x reference)
#include <cuda_runtime.h>
#include <cuda_bf16.h>

// Problem constants
#define BATCH   4
#define S_LEN   2048
#define D_MODEL 1024
#define NH      16
#define DHEAD   64
#define MROWS   (BATCH * S_LEN)     // 8192
#define NQKV    (3 * D_MODEL)       // 3072

// -------- scratch (no allocation allowed; __device__ globals) --------
__device__ float g_Wpack[D_MODEL * NQKV];        // [K=1024][N=3072] packed QKV weights
__device__ float g_bpack[NQKV];                  // packed QKV bias
__device__ float g_qkv[(size_t)MROWS * NQKV];    // Q|K|V  (B,S, 3*H*DH)
__device__ float g_z[(size_t)MROWS * D_MODEL];   // attention output (B,S,H,DH)

// ---------------------------------------------------------------------
// Pack kernel: W'[d][n] with n = which*1024 + h*64 + e, from W[h][d][e]
// ---------------------------------------------------------------------
__global__ void pack_qkv_kernel(const float* __restrict__ Wq,
                                const float* __restrict__ Wk,
                                const float* __restrict__ Wv,
                                const float* __restrict__ bq,
                                const float* __restrict__ bk,
                                const float* __restrict__ bv,
                                float* __restrict__ Wpack,
                                float* __restrict__ bpack)
{
    int idx = blockIdx.x * blockDim.x + threadIdx.x;
    if (idx < D_MODEL * NQKV) {
        int d = idx / NQKV;
        int n = idx - d * NQKV;
        int which = n >> 10;
        int nn = n & 1023;
        int h = nn >> 6;
        int e = nn & 63;
        const float* W = (which == 0) ? Wq : (which == 1) ? Wk : Wv;
        Wpack[idx] = W[(h * D_MODEL + d) * DHEAD + e];
    }
    if (idx < NQKV) {
        bpack[idx] = (idx < 1024) ? bq[idx] : (idx < 2048) ? bk[idx - 1024] : bv[idx - 2048];
    }
}

// ---------------------------------------------------------------------
// SGEMM: C[M,N] = A[M,K] @ B[K,N] + bias[N]
// 128x128 block tile, BK=8, 8x8 per thread, 256 threads.
// M,N,K all multiples of tile sizes (no bounds checks).
// ---------------------------------------------------------------------
#define GBM 128
#define GBN 128
#define GBK 8

__global__ __launch_bounds__(256) void sgemm_bias_kernel(
    const float* __restrict__ A, const float* __restrict__ B,
    const float* __restrict__ bias, float* __restrict__ C,
    int M, int N, int K)
{
    __shared__ float As[GBK][GBM];
    __shared__ float Bs[GBK][GBN];

    const int tid = threadIdx.x;
    const int bm = blockIdx.y * GBM;
    const int bn = blockIdx.x * GBN;

    const int arow = tid >> 1;            // 0..127
    const int acol = (tid & 1) << 2;      // 0 or 4
    const int brow = tid >> 5;            // 0..7
    const int bcol = (tid & 31) << 2;     // 0..124

    const int ty = tid >> 4;              // 0..15
    const int tx = tid & 15;              // 0..15

    float acc[8][8] = {};

    const float* Aptr = A + (size_t)(bm + arow) * K + acol;
    const float* Bptr = B + (size_t)brow * N + bn + bcol;

    for (int k0 = 0; k0 < K; k0 += GBK) {
        float4 av = *(const float4*)(Aptr + k0);
        As[acol + 0][arow] = av.x;
        As[acol + 1][arow] = av.y;
        As[acol + 2][arow] = av.z;
        As[acol + 3][arow] = av.w;
        *(float4*)&Bs[brow][bcol] = *(const float4*)(Bptr + (size_t)k0 * N);
        __syncthreads();

#pragma unroll
        for (int k = 0; k < GBK; k++) {
            float4 a0 = *(const float4*)&As[k][ty * 8];
            float4 a1 = *(const float4*)&As[k][ty * 8 + 4];
            float4 b0 = *(const float4*)&Bs[k][tx * 8];
            float4 b1 = *(const float4*)&Bs[k][tx * 8 + 4];
            float ar[8] = {a0.x, a0.y, a0.z, a0.w, a1.x, a1.y, a1.z, a1.w};
            float br[8] = {b0.x, b0.y, b0.z, b0.w, b1.x, b1.y, b1.z, b1.w};
#pragma unroll
            for (int i = 0; i < 8; i++)
#pragma unroll
                for (int j = 0; j < 8; j++)
                    acc[i][j] += ar[i] * br[j];
        }
        __syncthreads();
    }

#pragma unroll
    for (int i = 0; i < 8; i++) {
        int row = bm + ty * 8 + i;
#pragma unroll
        for (int j = 0; j < 8; j += 4) {
            int col = bn + tx * 8 + j;
            float4 v;
            v.x = acc[i][j + 0] + bias[col + 0];
            v.y = acc[i][j + 1] + bias[col + 1];
            v.z = acc[i][j + 2] + bias[col + 2];
            v.w = acc[i][j + 3] + bias[col + 3];
            *(float4*)(C + (size_t)row * N + col) = v;
        }
    }
}

// ---------------------------------------------------------------------
// Flash attention (fp32, causal). One block per (qtile, head, batch).
// 64x64 tiles, 256 threads, each thread computes 4x4 of S and 4x4 of O.
// Online softmax; P overwrites the K smem buffer between phases.
// ---------------------------------------------------------------------
__global__ __launch_bounds__(256) void flash_kernel(const float* __restrict__ qkv,
                                                    float* __restrict__ z)
{
    __shared__ float Qs[64 * 64];   // Q row-major [r][e]
    __shared__ float KPs[64 * 64];  // K transposed [e][r]; later P row-major [r][c]
    __shared__ float Vs[64 * 64];   // V row-major [r][e]

    const int b  = blockIdx.z;
    const int h  = blockIdx.y;
    const int qt = blockIdx.x;
    const int tid = threadIdx.x;
    const int ty = tid >> 4;   // 0..15 -> rows ty*4..ty*4+3
    const int tx = tid & 15;   // 0..15 -> cols tx*4..tx*4+3
    const int qbase = qt * 64;

    const float* base = qkv + (size_t)b * S_LEN * NQKV + h * DHEAD;

    // load Q tile
    for (int i = tid; i < 64 * 16; i += 256) {
        int r = i >> 4, c = (i & 15) << 2;
        *(float4*)&Qs[r * 64 + c] =
            *(const float4*)(base + (size_t)(qbase + r) * NQKV + c);
    }

    float o[4][4] = {};
    float m[4], l[4];
#pragma unroll
    for (int i = 0; i < 4; i++) { m[i] = -1e30f; l[i] = 0.0f; }

    const float scale = 0.125f; // 1/sqrt(64)

    for (int kt = 0; kt <= qt; kt++) {
        const int kbase = kt * 64;
        __syncthreads();  // previous PV phase done before overwriting K/V
        // load K (transposed into KPs) and V
        for (int i = tid; i < 64 * 16; i += 256) {
            int r = i >> 4, c = (i & 15) << 2;
            float4 kv = *(const float4*)(base + 1024 + (size_t)(kbase + r) * NQKV + c);
            KPs[(c + 0) * 64 + r] = kv.x;
            KPs[(c + 1) * 64 + r] = kv.y;
            KPs[(c + 2) * 64 + r] = kv.z;
            KPs[(c + 3) * 64 + r] = kv.w;
            *(float4*)&Vs[r * 64 + c] =
                *(const float4*)(base + 2048 + (size_t)(kbase + r) * NQKV + c);
        }
        __syncthreads();

        // S = Q @ K^T
        float s[4][4] = {};
#pragma unroll 8
        for (int e = 0; e < 64; e++) {
            float4 k4 = *(const float4*)&KPs[e * 64 + tx * 4];
#pragma unroll
            for (int i = 0; i < 4; i++) {
                float q = Qs[(ty * 4 + i) * 64 + e];
                s[i][0] += q * k4.x;
                s[i][1] += q * k4.y;
                s[i][2] += q * k4.z;
                s[i][3] += q * k4.w;
            }
        }

        // scale + causal mask (only diagonal tile can have masked entries)
        const bool diag = (kt == qt);
#pragma unroll
        for (int i = 0; i < 4; i++) {
            int qi = qbase + ty * 4 + i;
#pragma unroll
            for (int j = 0; j < 4; j++) {
                float v = s[i][j] * scale;
                if (diag && (kbase + tx * 4 + j > qi)) v = -1e30f;
                s[i][j] = v;
            }
        }

        // online softmax (row stats shared across the 16-lane tx group)
        float p[4][4];
#pragma unroll
        for (int i = 0; i < 4; i++) {
            float tm = fmaxf(fmaxf(s[i][0], s[i][1]), fmaxf(s[i][2], s[i][3]));
#pragma unroll
            for (int off = 8; off; off >>= 1)
                tm = fmaxf(tm, __shfl_xor_sync(0xffffffffu, tm, off));
            float mn = fmaxf(m[i], tm);
            float corr = __expf(m[i] - mn);
            m[i] = mn;
            float rs = 0.0f;
#pragma unroll
            for (int j = 0; j < 4; j++) { p[i][j] = __expf(s[i][j] - mn); rs += p[i][j]; }
#pragma unroll
            for (int off = 8; off; off >>= 1)
                rs += __shfl_xor_sync(0xffffffffu, rs, off);
            l[i] = l[i] * corr + rs;
#pragma unroll
            for (int j = 0; j < 4; j++) o[i][j] *= corr;
        }

        __syncthreads();  // all S-phase reads of KPs done
        // write P over KPs (row-major)
#pragma unroll
        for (int i = 0; i < 4; i++) {
            float4 pv = make_float4(p[i][0], p[i][1], p[i][2], p[i][3]);
            *(float4*)&KPs[(ty * 4 + i) * 64 + tx * 4] = pv;
        }
        __syncthreads();

        // O += P @ V
#pragma unroll 8
        for (int c = 0; c < 64; c++) {
            float4 v4 = *(const float4*)&Vs[c * 64 + tx * 4];
#pragma unroll
            for (int i = 0; i < 4; i++) {
                float pp = KPs[(ty * 4 + i) * 64 + c];
                o[i][0] += pp * v4.x;
                o[i][1] += pp * v4.y;
                o[i][2] += pp * v4.z;
                o[i][3] += pp * v4.w;
            }
        }
    }

    // epilogue: O /= l, write z (B,S,H,DH)
#pragma unroll
    for (int i = 0; i < 4; i++) {
        float inv = 1.0f / l[i];
        int row = b * S_LEN + qbase + ty * 4 + i;
        float4 ov = make_float4(o[i][0] * inv, o[i][1] * inv, o[i][2] * inv, o[i][3] * inv);
        *(float4*)&z[(size_t)row * D_MODEL + h * DHEAD + tx * 4] = ov;
    }
}

// ---------------------------------------------------------------------
extern "C" void kernel_launch(void* const* d_in, const int* in_sizes, int n_in,
                              void* d_out, int out_size)
{
    const float* x  = (const float*)d_in[0];
    const float* Wq = (const float*)d_in[1];
    const float* bq = (const float*)d_in[2];
    const float* Wk = (const float*)d_in[3];
    const float* bk = (const float*)d_in[4];
    const float* Wv = (const float*)d_in[5];
    const float* bv = (const float*)d_in[6];
    const float* Wo = (const float*)d_in[7];
    const float* bo = (const float*)d_in[8];
    float* out = (float*)d_out;

    float *Wpack, *bpack, *qkv, *z;
    cudaGetSymbolAddress((void**)&Wpack, g_Wpack);
    cudaGetSymbolAddress((void**)&bpack, g_bpack);
    cudaGetSymbolAddress((void**)&qkv,   g_qkv);
    cudaGetSymbolAddress((void**)&z,     g_z);

    // 1) pack QKV weights + bias
    pack_qkv_kernel<<<(D_MODEL * NQKV + 255) / 256, 256>>>(
        Wq, Wk, Wv, bq, bk, bv, Wpack, bpack);

    // 2) fused QKV projection: [8192,1024] @ [1024,3072]
    {
        dim3 grid(NQKV / GBN, MROWS / GBM);
        sgemm_bias_kernel<<<grid, 256>>>(x, Wpack, bpack, qkv, MROWS, NQKV, D_MODEL);
    }

    // 3) causal flash attention -> z (B,S,H,DH)
    {
        dim3 grid(S_LEN / 64, NH, BATCH);
        flash_kernel<<<grid, 256>>>(qkv, z);
    }

    // 4) output projection: [8192,1024] @ [1024,1024] + b_O
    {
        dim3 grid(D_MODEL / GBN, MROWS / GBM);
        sgemm_bias_kernel<<<grid, 256>>>(z, Wo, bo, out, MROWS, D_MODEL, D_MODEL);
    }
}

// round 5
// speedup vs baseline: 1.5138x; 1.5138x over previous
#include <cuda_runtime.h>
#include <cuda_bf16.h>
#include <cstdint>

// Problem constants
#define BATCH   4
#define S_LEN   2048
#define D_MODEL 1024
#define NH      16
#define DHEAD   64
#define MROWS   (BATCH * S_LEN)     // 8192
#define NQKV    (3 * D_MODEL)       // 3072

// -------- scratch (__device__ globals; no allocation allowed) --------
__device__ __align__(16) __nv_bfloat16 g_wqkv_hi[NQKV * D_MODEL];   // [N=3072][K=1024]
__device__ __align__(16) __nv_bfloat16 g_wqkv_lo[NQKV * D_MODEL];
__device__ __align__(16) __nv_bfloat16 g_wo_hi[D_MODEL * D_MODEL];  // [N=1024][K=1024]
__device__ __align__(16) __nv_bfloat16 g_wo_lo[D_MODEL * D_MODEL];
__device__ __align__(16) float g_bpack[NQKV];
__device__ __align__(16) __nv_bfloat16 g_x_hi[(size_t)MROWS * D_MODEL];
__device__ __align__(16) __nv_bfloat16 g_x_lo[(size_t)MROWS * D_MODEL];
__device__ __align__(16) __nv_bfloat16 g_z_hi[(size_t)MROWS * D_MODEL];
__device__ __align__(16) __nv_bfloat16 g_z_lo[(size_t)MROWS * D_MODEL];
__device__ __align__(16) float g_qkv[(size_t)MROWS * NQKV];   // Q|K|V fp32
__device__ __align__(16) float g_z[(size_t)MROWS * D_MODEL];  // attn out fp32

// ---------------------------------------------------------------------
// helpers (sm_80-era PTX only: ldmatrix / mma.sync / cp.async — all legal
// on plain compute_103; NO tcgen05 anywhere)
// ---------------------------------------------------------------------
__device__ __forceinline__ uint32_t smem_u32(const void* p) {
    uint32_t a;
    asm("{ .reg .u64 t; cvta.to.shared.u64 t, %1; cvt.u32.u64 %0, t; }" : "=r"(a) : "l"(p));
    return a;
}

__device__ __forceinline__ void ldsm4(uint32_t* r, uint32_t addr) {
    asm volatile("ldmatrix.sync.aligned.m8n8.x4.shared.b16 {%0,%1,%2,%3}, [%4];"
        : "=r"(r[0]), "=r"(r[1]), "=r"(r[2]), "=r"(r[3]) : "r"(addr));
}

__device__ __forceinline__ void mma16816(float* c, const uint32_t* a, const uint32_t* b) {
    asm volatile("mma.sync.aligned.m16n8k16.row.col.f32.bf16.bf16.f32 "
        "{%0,%1,%2,%3}, {%4,%5,%6,%7}, {%8,%9}, {%0,%1,%2,%3};"
        : "+f"(c[0]), "+f"(c[1]), "+f"(c[2]), "+f"(c[3])
        : "r"(a[0]), "r"(a[1]), "r"(a[2]), "r"(a[3]), "r"(b[0]), "r"(b[1]));
}

// ---------------------------------------------------------------------
// Weight pack + bf16 hi/lo split.
// qkv weights -> [N=3072][K=1024] (n = which*1024 + h*64 + e, k = d)
// Wo          -> [N=1024][K=1024] (n = d, k = h*64 + e)
// ---------------------------------------------------------------------
__global__ void pack_w_kernel(const float* __restrict__ Wq, const float* __restrict__ Wk,
                              const float* __restrict__ Wv, const float* __restrict__ Wo,
                              const float* __restrict__ bq, const float* __restrict__ bk,
                              const float* __restrict__ bv,
                              __nv_bfloat16* __restrict__ qh, __nv_bfloat16* __restrict__ ql,
                              __nv_bfloat16* __restrict__ oh, __nv_bfloat16* __restrict__ ol,
                              float* __restrict__ bpack)
{
    int idx = blockIdx.x * blockDim.x + threadIdx.x;
    if (idx < NQKV * D_MODEL) {
        int n = idx >> 10;
        int k = idx & 1023;
        int which = n >> 10;
        int nn = n & 1023;
        int h = nn >> 6;
        int e = nn & 63;
        const float* W = (which == 0) ? Wq : (which == 1) ? Wk : Wv;
        float v = W[(h * D_MODEL + k) * DHEAD + e];
        __nv_bfloat16 hi = __float2bfloat16(v);
        qh[idx] = hi;
        ql[idx] = __float2bfloat16(v - __bfloat162float(hi));
    }
    if (idx < D_MODEL * D_MODEL) {
        int n = idx >> 10;
        int k = idx & 1023;
        float v = Wo[k * D_MODEL + n];
        __nv_bfloat16 hi = __float2bfloat16(v);
        oh[idx] = hi;
        ol[idx] = __float2bfloat16(v - __bfloat162float(hi));
    }
    if (idx < NQKV)
        bpack[idx] = (idx < 1024) ? bq[idx] : (idx < 2048) ? bk[idx - 1024] : bv[idx - 2048];
}

// fp32 -> bf16 hi/lo split
__global__ void split_kernel(const float* __restrict__ in,
                             __nv_bfloat16* __restrict__ hi, __nv_bfloat16* __restrict__ lo,
                             int n)
{
    int i = blockIdx.x * blockDim.x + threadIdx.x;
    if (i < n) {
        float v = in[i];
        __nv_bfloat16 h = __float2bfloat16(v);
        hi[i] = h;
        lo[i] = __float2bfloat16(v - __bfloat162float(h));
    }
}

// ---------------------------------------------------------------------
// mma.sync bf16 GEMM with hi/lo split (3 terms), 128x128 block tile.
// A: [M][K] K-major bf16 (hi/lo).  B: [N][K] K-major bf16 (hi/lo).
// C[m][n] = sum_k A[m][k]*B[n][k] + bias[n], fp32 out.
// 8 warps; warp tile 64x32 (2x4 warp grid); BK=32; 2-stage cp.async.
// ---------------------------------------------------------------------
#define BK 32
#define ROWB 80                    // 64B data + 16B pad (ldmatrix conflict-free)
#define TILE_SB (128 * ROWB)       // 10240 B per tile
#define STAGE_SB (4 * TILE_SB)     // Ah, Al, Bh, Bl
#define MMA_SMEM (2 * STAGE_SB)    // 81920 B

__global__ __launch_bounds__(256) void mma_gemm_kernel(
    const __nv_bfloat16* __restrict__ Ah, const __nv_bfloat16* __restrict__ Al,
    const __nv_bfloat16* __restrict__ Bh, const __nv_bfloat16* __restrict__ Bl,
    const float* __restrict__ bias, float* __restrict__ C,
    int M, int N, int K)
{
    extern __shared__ char smem[];
    uint32_t sb = smem_u32(smem);
    const int tid  = threadIdx.x;
    const int lane = tid & 31;
    const int w    = tid >> 5;
    const int bm = blockIdx.y * 128;
    const int bn = blockIdx.x * 128;
    const int wm = (w >> 2) * 64;    // warp m offset
    const int wn = (w & 3) * 32;     // warp n offset

    float acc[4][4][4] = {};

    // cp.async load mapping: 2 threads/row, each thread 2 float4 per tile
    const int lrow = tid >> 1;
    const int c40  = (tid & 1) * 2;

    const __nv_bfloat16* srcs[4] = {
        Ah + (size_t)bm * K, Al + (size_t)bm * K,
        Bh + (size_t)bn * K, Bl + (size_t)bn * K };

    auto issue = [&](int ch, int stage) {
        uint32_t s0 = sb + stage * STAGE_SB;
        const int k0 = ch * BK;
#pragma unroll
        for (int t = 0; t < 4; t++) {
            const __nv_bfloat16* g = srcs[t] + (size_t)lrow * K + k0;
            uint32_t sdst = s0 + t * TILE_SB + lrow * ROWB;
#pragma unroll
            for (int i = 0; i < 2; i++) {
                int c4 = c40 + i;
                uint32_t d = sdst + c4 * 16;
                const void* src = (const void*)(g + c4 * 8);
                asm volatile("cp.async.ca.shared.global [%0], [%1], 16;" :: "r"(d), "l"(src));
            }
        }
        asm volatile("cp.async.commit_group;");
    };

    const int NCH = K / BK;
    issue(0, 0);

    // ldmatrix lane-derived components (constant across loop)
    const int a_r  = lane & 15;
    const int a_kk = (lane & 16) ? 8 : 0;
    const int b_n  = ((lane & 16) ? 8 : 0) + (lane & 7);
    const int b_kk = (lane & 8) ? 8 : 0;

    for (int ch = 0; ch < NCH; ch++) {
        const int stage = ch & 1;
        if (ch + 1 < NCH) {
            issue(ch + 1, stage ^ 1);
            asm volatile("cp.async.wait_group 1;");
        } else {
            asm volatile("cp.async.wait_group 0;");
        }
        __syncthreads();

        uint32_t s0 = sb + stage * STAGE_SB;
#pragma unroll
        for (int ks = 0; ks < 2; ks++) {
            const int kc = ks * 16;
            uint32_t ahf[4][4], alf[4][4], bhf[4][2], blf[4][2];
            // A fragments (hi + lo), 4 m16 tiles
#pragma unroll
            for (int mt = 0; mt < 4; mt++) {
                uint32_t off = (uint32_t)((wm + mt * 16 + a_r) * ROWB + (kc + a_kk) * 2);
                ldsm4(ahf[mt], s0 + 0 * TILE_SB + off);
                ldsm4(alf[mt], s0 + 1 * TILE_SB + off);
            }
            // B fragments (hi + lo), 2 x ldmatrix.x4 each covering n16
#pragma unroll
            for (int nt2 = 0; nt2 < 2; nt2++) {
                uint32_t off = (uint32_t)((wn + nt2 * 16 + b_n) * ROWB + (kc + b_kk) * 2);
                uint32_t rb[4];
                ldsm4(rb, s0 + 2 * TILE_SB + off);
                bhf[nt2 * 2][0] = rb[0]; bhf[nt2 * 2][1] = rb[1];
                bhf[nt2 * 2 + 1][0] = rb[2]; bhf[nt2 * 2 + 1][1] = rb[3];
                ldsm4(rb, s0 + 3 * TILE_SB + off);
                blf[nt2 * 2][0] = rb[0]; blf[nt2 * 2][1] = rb[1];
                blf[nt2 * 2 + 1][0] = rb[2]; blf[nt2 * 2 + 1][1] = rb[3];
            }
            // 3-term MMA: hi*hi + hi*lo + lo*hi
#pragma unroll
            for (int mt = 0; mt < 4; mt++)
#pragma unroll
                for (int nt = 0; nt < 4; nt++) {
                    mma16816(acc[mt][nt], ahf[mt], bhf[nt]);
                    mma16816(acc[mt][nt], ahf[mt], blf[nt]);
                    mma16816(acc[mt][nt], alf[mt], bhf[nt]);
                }
        }
        __syncthreads();
    }

    // epilogue: c0,c1 -> (row, col..col+1); c2,c3 -> (row+8, col..col+1)
    const int gid = lane >> 2;
    const int tig = lane & 3;
#pragma unroll
    for (int mt = 0; mt < 4; mt++) {
#pragma unroll
        for (int nt = 0; nt < 4; nt++) {
            int row = bm + wm + mt * 16 + gid;
            int col = bn + wn + nt * 8 + tig * 2;
            float b0 = bias[col], b1 = bias[col + 1];
            float2 v0 = make_float2(acc[mt][nt][0] + b0, acc[mt][nt][1] + b1);
            float2 v1 = make_float2(acc[mt][nt][2] + b0, acc[mt][nt][3] + b1);
            *(float2*)(C + (size_t)row * N + col) = v0;
            *(float2*)(C + (size_t)(row + 8) * N + col) = v1;
        }
    }
}

// ---------------------------------------------------------------------
// Flash attention (fp32, causal) — unchanged (known passing).
// ---------------------------------------------------------------------
__global__ __launch_bounds__(256) void flash_kernel(const float* __restrict__ qkv,
                                                    float* __restrict__ z)
{
    __shared__ float Qs[64 * 64];
    __shared__ float KPs[64 * 64];
    __shared__ float Vs[64 * 64];

    const int b  = blockIdx.z;
    const int h  = blockIdx.y;
    const int qt = blockIdx.x;
    const int tid = threadIdx.x;
    const int ty = tid >> 4;
    const int tx = tid & 15;
    const int qbase = qt * 64;

    const float* base = qkv + (size_t)b * S_LEN * NQKV + h * DHEAD;

    for (int i = tid; i < 64 * 16; i += 256) {
        int r = i >> 4, c = (i & 15) << 2;
        *(float4*)&Qs[r * 64 + c] =
            *(const float4*)(base + (size_t)(qbase + r) * NQKV + c);
    }

    float o[4][4] = {};
    float m[4], l[4];
#pragma unroll
    for (int i = 0; i < 4; i++) { m[i] = -1e30f; l[i] = 0.0f; }

    const float scale = 0.125f;

    for (int kt = 0; kt <= qt; kt++) {
        const int kbase = kt * 64;
        __syncthreads();
        for (int i = tid; i < 64 * 16; i += 256) {
            int r = i >> 4, c = (i & 15) << 2;
            float4 kv = *(const float4*)(base + 1024 + (size_t)(kbase + r) * NQKV + c);
            KPs[(c + 0) * 64 + r] = kv.x;
            KPs[(c + 1) * 64 + r] = kv.y;
            KPs[(c + 2) * 64 + r] = kv.z;
            KPs[(c + 3) * 64 + r] = kv.w;
            *(float4*)&Vs[r * 64 + c] =
                *(const float4*)(base + 2048 + (size_t)(kbase + r) * NQKV + c);
        }
        __syncthreads();

        float s[4][4] = {};
#pragma unroll 8
        for (int e = 0; e < 64; e++) {
            float4 k4 = *(const float4*)&KPs[e * 64 + tx * 4];
#pragma unroll
            for (int i = 0; i < 4; i++) {
                float q = Qs[(ty * 4 + i) * 64 + e];
                s[i][0] += q * k4.x;
                s[i][1] += q * k4.y;
                s[i][2] += q * k4.z;
                s[i][3] += q * k4.w;
            }
        }

        const bool diag = (kt == qt);
#pragma unroll
        for (int i = 0; i < 4; i++) {
            int qi = qbase + ty * 4 + i;
#pragma unroll
            for (int j = 0; j < 4; j++) {
                float v = s[i][j] * scale;
                if (diag && (kbase + tx * 4 + j > qi)) v = -1e30f;
                s[i][j] = v;
            }
        }

        float p[4][4];
#pragma unroll
        for (int i = 0; i < 4; i++) {
            float tm = fmaxf(fmaxf(s[i][0], s[i][1]), fmaxf(s[i][2], s[i][3]));
#pragma unroll
            for (int off = 8; off; off >>= 1)
                tm = fmaxf(tm, __shfl_xor_sync(0xffffffffu, tm, off));
            float mn = fmaxf(m[i], tm);
            float corr = __expf(m[i] - mn);
            m[i] = mn;
            float rs = 0.0f;
#pragma unroll
            for (int j = 0; j < 4; j++) { p[i][j] = __expf(s[i][j] - mn); rs += p[i][j]; }
#pragma unroll
            for (int off = 8; off; off >>= 1)
                rs += __shfl_xor_sync(0xffffffffu, rs, off);
            l[i] = l[i] * corr + rs;
#pragma unroll
            for (int j = 0; j < 4; j++) o[i][j] *= corr;
        }

        __syncthreads();
#pragma unroll
        for (int i = 0; i < 4; i++) {
            float4 pv = make_float4(p[i][0], p[i][1], p[i][2], p[i][3]);
            *(float4*)&KPs[(ty * 4 + i) * 64 + tx * 4] = pv;
        }
        __syncthreads();

#pragma unroll 8
        for (int c = 0; c < 64; c++) {
            float4 v4 = *(const float4*)&Vs[c * 64 + tx * 4];
#pragma unroll
            for (int i = 0; i < 4; i++) {
                float pp = KPs[(ty * 4 + i) * 64 + c];
                o[i][0] += pp * v4.x;
                o[i][1] += pp * v4.y;
                o[i][2] += pp * v4.z;
                o[i][3] += pp * v4.w;
            }
        }
    }

#pragma unroll
    for (int i = 0; i < 4; i++) {
        float inv = 1.0f / l[i];
        int row = b * S_LEN + qbase + ty * 4 + i;
        float4 ov = make_float4(o[i][0] * inv, o[i][1] * inv, o[i][2] * inv, o[i][3] * inv);
        *(float4*)&z[(size_t)row * D_MODEL + h * DHEAD + tx * 4] = ov;
    }
}

// ---------------------------------------------------------------------
extern "C" void kernel_launch(void* const* d_in, const int* in_sizes, int n_in,
                              void* d_out, int out_size)
{
    const float* x  = (const float*)d_in[0];
    const float* Wq = (const float*)d_in[1];
    const float* bq = (const float*)d_in[2];
    const float* Wk = (const float*)d_in[3];
    const float* bk = (const float*)d_in[4];
    const float* Wv = (const float*)d_in[5];
    const float* bv = (const float*)d_in[6];
    const float* Wo = (const float*)d_in[7];
    const float* bo = (const float*)d_in[8];
    float* out = (float*)d_out;

    // not a stream op; safe to call every invocation (incl. during capture)
    cudaFuncSetAttribute(mma_gemm_kernel,
                         cudaFuncAttributeMaxDynamicSharedMemorySize, MMA_SMEM);

    __nv_bfloat16 *qh, *ql, *oh, *ol, *xh, *xl, *zh, *zl;
    float *bpack, *qkv, *z;
    cudaGetSymbolAddress((void**)&qh, g_wqkv_hi);
    cudaGetSymbolAddress((void**)&ql, g_wqkv_lo);
    cudaGetSymbolAddress((void**)&oh, g_wo_hi);
    cudaGetSymbolAddress((void**)&ol, g_wo_lo);
    cudaGetSymbolAddress((void**)&xh, g_x_hi);
    cudaGetSymbolAddress((void**)&xl, g_x_lo);
    cudaGetSymbolAddress((void**)&zh, g_z_hi);
    cudaGetSymbolAddress((void**)&zl, g_z_lo);
    cudaGetSymbolAddress((void**)&bpack, g_bpack);
    cudaGetSymbolAddress((void**)&qkv, g_qkv);
    cudaGetSymbolAddress((void**)&z, g_z);

    // 1) pack + split weights, pack bias
    pack_w_kernel<<<(NQKV * D_MODEL + 255) / 256, 256>>>(
        Wq, Wk, Wv, Wo, bq, bk, bv, qh, ql, oh, ol, bpack);

    // 2) split x to bf16 hi/lo
    {
        int n = MROWS * D_MODEL;
        split_kernel<<<(n + 255) / 256, 256>>>(x, xh, xl, n);
    }

    // 3) QKV projection: [8192,1024] x [3072,1024]^T -> [8192,3072]
    {
        dim3 grid(NQKV / 128, MROWS / 128);
        mma_gemm_kernel<<<grid, 256, MMA_SMEM>>>(
            xh, xl, qh, ql, bpack, qkv, MROWS, NQKV, D_MODEL);
    }

    // 4) causal flash attention -> z (B,S,H,DH)
    {
        dim3 grid(S_LEN / 64, NH, BATCH);
        flash_kernel<<<grid, 256>>>(qkv, z);
    }

    // 5) split z
    {
        int n = MROWS * D_MODEL;
        split_kernel<<<(n + 255) / 256, 256>>>(z, zh, zl, n);
    }

    // 6) output projection: [8192,1024] x [1024,1024]^T + b_O
    {
        dim3 grid(D_MODEL / 128, MROWS / 128);
        mma_gemm_kernel<<<grid, 256, MMA_SMEM>>>(
            zh, zl, oh, ol, bo, out, MROWS, D_MODEL, D_MODEL);
    }
}

// round 12
// speedup vs baseline: 2.6207x; 1.7312x over previous
#include <cuda_runtime.h>
#include <cuda_bf16.h>
#include <cstdint>

// Problem constants
#define BATCH   4
#define S_LEN   2048
#define D_MODEL 1024
#define NH      16
#define DHEAD   64
#define MROWS   (BATCH * S_LEN)     // 8192
#define NQKV    (3 * D_MODEL)       // 3072

// -------- scratch (__device__ globals; no allocation allowed) --------
__device__ __align__(16) __nv_bfloat16 g_wqkv_hi[NQKV * D_MODEL];   // [N=3072][K=1024]
__device__ __align__(16) __nv_bfloat16 g_wqkv_lo[NQKV * D_MODEL];
__device__ __align__(16) __nv_bfloat16 g_wo_hi[D_MODEL * D_MODEL];  // [N=1024][K=1024]
__device__ __align__(16) __nv_bfloat16 g_wo_lo[D_MODEL * D_MODEL];
__device__ __align__(16) float g_bpack[NQKV];
__device__ __align__(16) __nv_bfloat16 g_x_hi[(size_t)MROWS * D_MODEL];
__device__ __align__(16) __nv_bfloat16 g_x_lo[(size_t)MROWS * D_MODEL];
__device__ __align__(16) __nv_bfloat16 g_qkv_hi[(size_t)MROWS * NQKV];
__device__ __align__(16) __nv_bfloat16 g_qkv_lo[(size_t)MROWS * NQKV];
__device__ __align__(16) __nv_bfloat16 g_z_hi[(size_t)MROWS * D_MODEL];
__device__ __align__(16) __nv_bfloat16 g_z_lo[(size_t)MROWS * D_MODEL];

// ---------------------------------------------------------------------
// helpers (sm_80/90-era PTX only — legal on plain compute_103)
// ---------------------------------------------------------------------
__device__ __forceinline__ uint32_t smem_u32(const void* p) {
    uint32_t a;
    asm("{ .reg .u64 t; cvta.to.shared.u64 t, %1; cvt.u32.u64 %0, t; }" : "=r"(a) : "l"(p));
    return a;
}
__device__ __forceinline__ void ldsm4(uint32_t* r, uint32_t addr) {
    asm volatile("ldmatrix.sync.aligned.m8n8.x4.shared.b16 {%0,%1,%2,%3}, [%4];"
        : "=r"(r[0]), "=r"(r[1]), "=r"(r[2]), "=r"(r[3]) : "r"(addr));
}
__device__ __forceinline__ void ldsm4t(uint32_t* r, uint32_t addr) {
    asm volatile("ldmatrix.sync.aligned.m8n8.x4.trans.shared.b16 {%0,%1,%2,%3}, [%4];"
        : "=r"(r[0]), "=r"(r[1]), "=r"(r[2]), "=r"(r[3]) : "r"(addr));
}
__device__ __forceinline__ void mma16816(float* c, const uint32_t* a, const uint32_t* b) {
    asm volatile("mma.sync.aligned.m16n8k16.row.col.f32.bf16.bf16.f32 "
        "{%0,%1,%2,%3}, {%4,%5,%6,%7}, {%8,%9}, {%0,%1,%2,%3};"
        : "+f"(c[0]), "+f"(c[1]), "+f"(c[2]), "+f"(c[3])
        : "r"(a[0]), "r"(a[1]), "r"(a[2]), "r"(a[3]), "r"(b[0]), "r"(b[1]));
}
__device__ __forceinline__ void cpasync16(uint32_t dst, const void* src) {
    asm volatile("cp.async.ca.shared.global [%0], [%1], 16;" :: "r"(dst), "l"(src));
}
// pack (a -> low half, b -> high half) hi parts and residual parts
__device__ __forceinline__ void split2(float a, float b, uint32_t& hi, uint32_t& lo) {
    __nv_bfloat16 ha = __float2bfloat16(a), hb = __float2bfloat16(b);
    float ra = a - __bfloat162float(ha);
    float rb = b - __bfloat162float(hb);
    __nv_bfloat16 la = __float2bfloat16(ra), lb = __float2bfloat16(rb);
    __nv_bfloat162 hv; hv.x = ha; hv.y = hb;
    __nv_bfloat162 lv; lv.x = la; lv.y = lb;
    hi = *reinterpret_cast<uint32_t*>(&hv);
    lo = *reinterpret_cast<uint32_t*>(&lv);
}

// ---------------------------------------------------------------------
// Weight pack + bf16 hi/lo split (unchanged).
// ---------------------------------------------------------------------
__global__ void pack_w_kernel(const float* __restrict__ Wq, const float* __restrict__ Wk,
                              const float* __restrict__ Wv, const float* __restrict__ Wo,
                              const float* __restrict__ bq, const float* __restrict__ bk,
                              const float* __restrict__ bv,
                              __nv_bfloat16* __restrict__ qh, __nv_bfloat16* __restrict__ ql,
                              __nv_bfloat16* __restrict__ oh, __nv_bfloat16* __restrict__ ol,
                              float* __restrict__ bpack)
{
    int idx = blockIdx.x * blockDim.x + threadIdx.x;
    if (idx < NQKV * D_MODEL) {
        int n = idx >> 10;
        int k = idx & 1023;
        int which = n >> 10;
        int nn = n & 1023;
        int h = nn >> 6;
        int e = nn & 63;
        const float* W = (which == 0) ? Wq : (which == 1) ? Wk : Wv;
        float v = W[(h * D_MODEL + k) * DHEAD + e];
        __nv_bfloat16 hi = __float2bfloat16(v);
        qh[idx] = hi;
        ql[idx] = __float2bfloat16(v - __bfloat162float(hi));
    }
    if (idx < D_MODEL * D_MODEL) {
        int n = idx >> 10;
        int k = idx & 1023;
        float v = Wo[k * D_MODEL + n];
        __nv_bfloat16 hi = __float2bfloat16(v);
        oh[idx] = hi;
        ol[idx] = __float2bfloat16(v - __bfloat162float(hi));
    }
    if (idx < NQKV)
        bpack[idx] = (idx < 1024) ? bq[idx] : (idx < 2048) ? bk[idx - 1024] : bv[idx - 2048];
}

__global__ void split_kernel(const float* __restrict__ in,
                             __nv_bfloat16* __restrict__ hi, __nv_bfloat16* __restrict__ lo,
                             int n)
{
    int i = blockIdx.x * blockDim.x + threadIdx.x;
    if (i < n) {
        float v = in[i];
        __nv_bfloat16 h = __float2bfloat16(v);
        hi[i] = h;
        lo[i] = __float2bfloat16(v - __bfloat162float(h));
    }
}

// ---------------------------------------------------------------------
// mma.sync bf16 GEMM, hi/lo split (3 terms), 128x128 block tile (R5, passing).
// Optional bf16 hi/lo output (OutHi/OutLo) instead of fp32 C.
// ---------------------------------------------------------------------
#define BK 32
#define ROWB 80
#define TILE_SB (128 * ROWB)
#define STAGE_SB (4 * TILE_SB)
#define MMA_SMEM (2 * STAGE_SB)    // 81920 B

__global__ __launch_bounds__(256) void mma_gemm_kernel(
    const __nv_bfloat16* __restrict__ Ah, const __nv_bfloat16* __restrict__ Al,
    const __nv_bfloat16* __restrict__ Bh, const __nv_bfloat16* __restrict__ Bl,
    const float* __restrict__ bias, float* __restrict__ C,
    __nv_bfloat16* __restrict__ OutHi, __nv_bfloat16* __restrict__ OutLo,
    int M, int N, int K)
{
    extern __shared__ char smem[];
    uint32_t sb = smem_u32(smem);
    const int tid  = threadIdx.x;
    const int lane = tid & 31;
    const int w    = tid >> 5;
    const int bm = blockIdx.y * 128;
    const int bn = blockIdx.x * 128;
    const int wm = (w >> 2) * 64;
    const int wn = (w & 3) * 32;

    float acc[4][4][4] = {};

    const int lrow = tid >> 1;
    const int c40  = (tid & 1) * 2;

    const __nv_bfloat16* srcs[4] = {
        Ah + (size_t)bm * K, Al + (size_t)bm * K,
        Bh + (size_t)bn * K, Bl + (size_t)bn * K };

    auto issue = [&](int ch, int stage) {
        uint32_t s0 = sb + stage * STAGE_SB;
        const int k0 = ch * BK;
#pragma unroll
        for (int t = 0; t < 4; t++) {
            const __nv_bfloat16* g = srcs[t] + (size_t)lrow * K + k0;
            uint32_t sdst = s0 + t * TILE_SB + lrow * ROWB;
#pragma unroll
            for (int i = 0; i < 2; i++) {
                int c4 = c40 + i;
                cpasync16(sdst + c4 * 16, (const void*)(g + c4 * 8));
            }
        }
        asm volatile("cp.async.commit_group;");
    };

    const int NCH = K / BK;
    issue(0, 0);

    const int a_r  = lane & 15;
    const int a_kk = (lane & 16) ? 8 : 0;
    const int b_n  = ((lane & 16) ? 8 : 0) + (lane & 7);
    const int b_kk = (lane & 8) ? 8 : 0;

    for (int ch = 0; ch < NCH; ch++) {
        const int stage = ch & 1;
        if (ch + 1 < NCH) {
            issue(ch + 1, stage ^ 1);
            asm volatile("cp.async.wait_group 1;");
        } else {
            asm volatile("cp.async.wait_group 0;");
        }
        __syncthreads();

        uint32_t s0 = sb + stage * STAGE_SB;
#pragma unroll
        for (int ks = 0; ks < 2; ks++) {
            const int kc = ks * 16;
            uint32_t ahf[4][4], alf[4][4], bhf[4][2], blf[4][2];
#pragma unroll
            for (int mt = 0; mt < 4; mt++) {
                uint32_t off = (uint32_t)((wm + mt * 16 + a_r) * ROWB + (kc + a_kk) * 2);
                ldsm4(ahf[mt], s0 + 0 * TILE_SB + off);
                ldsm4(alf[mt], s0 + 1 * TILE_SB + off);
            }
#pragma unroll
            for (int nt2 = 0; nt2 < 2; nt2++) {
                uint32_t off = (uint32_t)((wn + nt2 * 16 + b_n) * ROWB + (kc + b_kk) * 2);
                uint32_t rb[4];
                ldsm4(rb, s0 + 2 * TILE_SB + off);
                bhf[nt2 * 2][0] = rb[0]; bhf[nt2 * 2][1] = rb[1];
                bhf[nt2 * 2 + 1][0] = rb[2]; bhf[nt2 * 2 + 1][1] = rb[3];
                ldsm4(rb, s0 + 3 * TILE_SB + off);
                blf[nt2 * 2][0] = rb[0]; blf[nt2 * 2][1] = rb[1];
                blf[nt2 * 2 + 1][0] = rb[2]; blf[nt2 * 2 + 1][1] = rb[3];
            }
#pragma unroll
            for (int mt = 0; mt < 4; mt++)
#pragma unroll
                for (int nt = 0; nt < 4; nt++) {
                    mma16816(acc[mt][nt], ahf[mt], bhf[nt]);
                    mma16816(acc[mt][nt], ahf[mt], blf[nt]);
                    mma16816(acc[mt][nt], alf[mt], bhf[nt]);
                }
        }
        __syncthreads();
    }

    const int gid = lane >> 2;
    const int tig = lane & 3;
#pragma unroll
    for (int mt = 0; mt < 4; mt++) {
#pragma unroll
        for (int nt = 0; nt < 4; nt++) {
            int row = bm + wm + mt * 16 + gid;
            int col = bn + wn + nt * 8 + tig * 2;
            float b0 = bias[col], b1 = bias[col + 1];
            float v00 = acc[mt][nt][0] + b0, v01 = acc[mt][nt][1] + b1;
            float v10 = acc[mt][nt][2] + b0, v11 = acc[mt][nt][3] + b1;
            if (OutHi) {
                uint32_t h0, l0, h1, l1;
                split2(v00, v01, h0, l0);
                split2(v10, v11, h1, l1);
                size_t i0 = ((size_t)row * N + col) >> 1;
                size_t i1 = ((size_t)(row + 8) * N + col) >> 1;
                ((uint32_t*)OutHi)[i0] = h0;
                ((uint32_t*)OutLo)[i0] = l0;
                ((uint32_t*)OutHi)[i1] = h1;
                ((uint32_t*)OutLo)[i1] = l1;
            } else {
                *(float2*)(C + (size_t)row * N + col) = make_float2(v00, v01);
                *(float2*)(C + (size_t)(row + 8) * N + col) = make_float2(v10, v11);
            }
        }
    }
}

// ---------------------------------------------------------------------
// Flash attention on mma.sync (bf16 hi/lo, 3-term), causal.
// Block = 128 q-rows x (head, batch). 8 warps x 16 q-rows. K-tile = 64.
// Q frags in registers; K/V double-buffered cp.async; P stays in registers.
// ---------------------------------------------------------------------
#define FST 144                    // smem row stride bytes (64 bf16 + 16B pad)
#define FS_QH 0
#define FS_QL (128 * FST)          // 18432
#define FS_KV (2 * 128 * FST)      // 36864
#define FS_STAGE (4 * 64 * FST)    // 36864: KH, KL, VH, VL
#define FS_SMEM (FS_KV + 2 * FS_STAGE)   // 110592

__global__ __launch_bounds__(256, 1) void flash_mma_kernel(
    const __nv_bfloat16* __restrict__ qkvh, const __nv_bfloat16* __restrict__ qkvl,
    __nv_bfloat16* __restrict__ zh, __nv_bfloat16* __restrict__ zl)
{
    extern __shared__ char smem[];
    uint32_t sb = smem_u32(smem);
    const int qt = blockIdx.x;          // 16 tiles of 128 rows
    const int h  = blockIdx.y;
    const int b  = blockIdx.z;
    const int tid  = threadIdx.x;
    const int lane = tid & 31;
    const int w    = tid >> 5;
    const int wq   = w * 16;            // warp q-row offset in tile
    const int qbase = qt * 128;
    const size_t rowbase = (size_t)b * S_LEN;

    const int gid = lane >> 2;
    const int tig = lane & 3;
    const int a_r  = lane & 15;
    const int a_kk = (lane & 16) ? 8 : 0;
    const int b_n  = ((lane & 16) ? 8 : 0) + (lane & 7);
    const int b_kk = (lane & 8) ? 8 : 0;
    const int t_r  = lane & 15;                 // trans ldsm row (c dim)
    const int t_c  = (lane >> 4) << 3;          // trans ldsm col group (e dim)

    // ---- issue Q (group 0): 2 tiles x 128 rows; thread -> one row
    {
        int tile = tid >> 7;            // 0=hi 1=lo
        int r = tid & 127;
        const __nv_bfloat16* src = (tile ? qkvl : qkvh)
            + (rowbase + qbase + r) * NQKV + h * DHEAD;
        uint32_t dst = sb + (tile ? FS_QL : FS_QH) + r * FST;
#pragma unroll
        for (int c = 0; c < 8; c++)
            cpasync16(dst + c * 16, (const void*)(src + c * 8));
        asm volatile("cp.async.commit_group;");
    }

    const int nkt = 2 * qt + 2;

    // ---- KV issue lambda: 4 tiles x 64 rows; thread -> one row
    auto issueKV = [&](int kt, int stage) {
        int tile = tid >> 6;            // 0 KH, 1 KL, 2 VH, 3 VL
        int r = tid & 63;
        const __nv_bfloat16* base = (tile & 1) ? qkvl : qkvh;
        int which = (tile >> 1) ? 2048 : 1024;   // K or V
        const __nv_bfloat16* src = base
            + (rowbase + (size_t)kt * 64 + r) * NQKV + which + h * DHEAD;
        uint32_t dst = sb + FS_KV + stage * FS_STAGE + tile * (64 * FST) + r * FST;
#pragma unroll
        for (int c = 0; c < 8; c++)
            cpasync16(dst + c * 16, (const void*)(src + c * 8));
        asm volatile("cp.async.commit_group;");
    };

    issueKV(0, 0);

    uint32_t qhf[4][4], qlf[4][4];      // Q fragments, loaded at kt==0
    float o[8][4] = {};
    float m0 = -1e30f, m1 = -1e30f, l0 = 0.0f, l1 = 0.0f;
    const float scale = 0.125f;

    for (int kt = 0; kt < nkt; kt++) {
        const int stage = kt & 1;
        if (kt + 1 < nkt) {
            issueKV(kt + 1, stage ^ 1);
            asm volatile("cp.async.wait_group 1;");
        } else {
            asm volatile("cp.async.wait_group 0;");
        }
        __syncthreads();

        if (kt == 0) {
#pragma unroll
            for (int j = 0; j < 4; j++) {
                uint32_t off = (uint32_t)((wq + a_r) * FST + (16 * j + a_kk) * 2);
                ldsm4(qhf[j], sb + FS_QH + off);
                ldsm4(qlf[j], sb + FS_QL + off);
            }
        }

        uint32_t skv = sb + FS_KV + stage * FS_STAGE;
        // ---- S = Q @ K^T (3-term), 8 n8-tiles x fp32
        float s[8][4] = {};
#pragma unroll
        for (int j = 0; j < 4; j++) {           // e k-steps
#pragma unroll
            for (int g = 0; g < 4; g++) {       // n16 groups over 64 k-cols
                uint32_t off = (uint32_t)((g * 16 + b_n) * FST + (16 * j + b_kk) * 2);
                uint32_t kh[4], kl[4];
                ldsm4(kh, skv + 0 * (64 * FST) + off);
                ldsm4(kl, skv + 1 * (64 * FST) + off);
                uint32_t bh0[2] = {kh[0], kh[1]}, bh1[2] = {kh[2], kh[3]};
                uint32_t bl0[2] = {kl[0], kl[1]}, bl1[2] = {kl[2], kl[3]};
                mma16816(s[2 * g], qhf[j], bh0);
                mma16816(s[2 * g], qhf[j], bl0);
                mma16816(s[2 * g], qlf[j], bh0);
                mma16816(s[2 * g + 1], qhf[j], bh1);
                mma16816(s[2 * g + 1], qhf[j], bl1);
                mma16816(s[2 * g + 1], qlf[j], bh1);
            }
        }

        // ---- scale + causal mask
        const int kbase = kt * 64;
        const bool need_mask = (kt >= 2 * qt);
        const int row0 = qbase + wq + gid;
        const int row1 = row0 + 8;
#pragma unroll
        for (int nt = 0; nt < 8; nt++) {
            int col = kbase + nt * 8 + tig * 2;
            s[nt][0] *= scale; s[nt][1] *= scale;
            s[nt][2] *= scale; s[nt][3] *= scale;
            if (need_mask) {
                if (col     > row0) s[nt][0] = -1e30f;
                if (col + 1 > row0) s[nt][1] = -1e30f;
                if (col     > row1) s[nt][2] = -1e30f;
                if (col + 1 > row1) s[nt][3] = -1e30f;
            }
        }

        // ---- online softmax (rows row0, row1; quad = 4 lanes share a row)
        float rm0 = -1e30f, rm1 = -1e30f;
#pragma unroll
        for (int nt = 0; nt < 8; nt++) {
            rm0 = fmaxf(rm0, fmaxf(s[nt][0], s[nt][1]));
            rm1 = fmaxf(rm1, fmaxf(s[nt][2], s[nt][3]));
        }
        rm0 = fmaxf(rm0, __shfl_xor_sync(0xffffffffu, rm0, 1));
        rm0 = fmaxf(rm0, __shfl_xor_sync(0xffffffffu, rm0, 2));
        rm1 = fmaxf(rm1, __shfl_xor_sync(0xffffffffu, rm1, 1));
        rm1 = fmaxf(rm1, __shfl_xor_sync(0xffffffffu, rm1, 2));
        float m0n = fmaxf(m0, rm0);
        float m1n = fmaxf(m1, rm1);
        float corr0 = __expf(m0 - m0n);
        float corr1 = __expf(m1 - m1n);
        m0 = m0n; m1 = m1n;
        float rs0 = 0.0f, rs1 = 0.0f;
#pragma unroll
        for (int nt = 0; nt < 8; nt++) {
            s[nt][0] = __expf(s[nt][0] - m0n);
            s[nt][1] = __expf(s[nt][1] - m0n);
            s[nt][2] = __expf(s[nt][2] - m1n);
            s[nt][3] = __expf(s[nt][3] - m1n);
            rs0 += s[nt][0] + s[nt][1];
            rs1 += s[nt][2] + s[nt][3];
        }
        rs0 += __shfl_xor_sync(0xffffffffu, rs0, 1);
        rs0 += __shfl_xor_sync(0xffffffffu, rs0, 2);
        rs1 += __shfl_xor_sync(0xffffffffu, rs1, 1);
        rs1 += __shfl_xor_sync(0xffffffffu, rs1, 2);
        l0 = l0 * corr0 + rs0;
        l1 = l1 * corr1 + rs1;
#pragma unroll
        for (int nt = 0; nt < 8; nt++) {
            o[nt][0] *= corr0; o[nt][1] *= corr0;
            o[nt][2] *= corr1; o[nt][3] *= corr1;
        }

        // ---- P fragments (hi/lo) directly from S registers
        uint32_t pah[4][4], pal[4][4];
#pragma unroll
        for (int j = 0; j < 4; j++) {
            int t0 = 2 * j, t1 = 2 * j + 1;
            split2(s[t0][0], s[t0][1], pah[j][0], pal[j][0]);
            split2(s[t0][2], s[t0][3], pah[j][1], pal[j][1]);
            split2(s[t1][0], s[t1][1], pah[j][2], pal[j][2]);
            split2(s[t1][2], s[t1][3], pah[j][3], pal[j][3]);
        }

        // ---- O += P @ V (V fragments via ldmatrix.trans; 3-term)
#pragma unroll
        for (int j = 0; j < 4; j++) {           // c k-steps
#pragma unroll
            for (int g = 0; g < 4; g++) {       // e n16 groups
                uint32_t off = (uint32_t)((16 * j + t_r) * FST + (g * 16 + t_c) * 2);
                uint32_t vh[4], vl[4];
                ldsm4t(vh, skv + 2 * (64 * FST) + off);
                ldsm4t(vl, skv + 3 * (64 * FST) + off);
                uint32_t bh0[2] = {vh[0], vh[1]}, bh1[2] = {vh[2], vh[3]};
                uint32_t bl0[2] = {vl[0], vl[1]}, bl1[2] = {vl[2], vl[3]};
                mma16816(o[2 * g], pah[j], bh0);
                mma16816(o[2 * g], pah[j], bl0);
                mma16816(o[2 * g], pal[j], bh0);
                mma16816(o[2 * g + 1], pah[j], bh1);
                mma16816(o[2 * g + 1], pah[j], bl1);
                mma16816(o[2 * g + 1], pal[j], bh1);
            }
        }
        __syncthreads();   // all reads of this stage done before reuse
    }

    // ---- epilogue: z = O / l, split hi/lo, store
    float inv0 = 1.0f / l0;
    float inv1 = 1.0f / l1;
    size_t r0 = (rowbase + qbase + wq + gid) * D_MODEL + h * DHEAD;
    size_t r1 = r0 + 8 * D_MODEL;
#pragma unroll
    for (int nt = 0; nt < 8; nt++) {
        int col = nt * 8 + tig * 2;
        uint32_t h0, lo0, h1, lo1;
        split2(o[nt][0] * inv0, o[nt][1] * inv0, h0, lo0);
        split2(o[nt][2] * inv1, o[nt][3] * inv1, h1, lo1);
        ((uint32_t*)zh)[(r0 + col) >> 1] = h0;
        ((uint32_t*)zl)[(r0 + col) >> 1] = lo0;
        ((uint32_t*)zh)[(r1 + col) >> 1] = h1;
        ((uint32_t*)zl)[(r1 + col) >> 1] = lo1;
    }
}

// ---------------------------------------------------------------------
extern "C" void kernel_launch(void* const* d_in, const int* in_sizes, int n_in,
                              void* d_out, int out_size)
{
    const float* x  = (const float*)d_in[0];
    const float* Wq = (const float*)d_in[1];
    const float* bq = (const float*)d_in[2];
    const float* Wk = (const float*)d_in[3];
    const float* bk = (const float*)d_in[4];
    const float* Wv = (const float*)d_in[5];
    const float* bv = (const float*)d_in[6];
    const float* Wo = (const float*)d_in[7];
    const float* bo = (const float*)d_in[8];
    float* out = (float*)d_out;

    cudaFuncSetAttribute(mma_gemm_kernel,
                         cudaFuncAttributeMaxDynamicSharedMemorySize, MMA_SMEM);
    cudaFuncSetAttribute(flash_mma_kernel,
                         cudaFuncAttributeMaxDynamicSharedMemorySize, FS_SMEM);

    __nv_bfloat16 *qh, *ql, *oh, *ol, *xh, *xl, *qkvh, *qkvl, *zh, *zl;
    float *bpack;
    cudaGetSymbolAddress((void**)&qh, g_wqkv_hi);
    cudaGetSymbolAddress((void**)&ql, g_wqkv_lo);
    cudaGetSymbolAddress((void**)&oh, g_wo_hi);
    cudaGetSymbolAddress((void**)&ol, g_wo_lo);
    cudaGetSymbolAddress((void**)&xh, g_x_hi);
    cudaGetSymbolAddress((void**)&xl, g_x_lo);
    cudaGetSymbolAddress((void**)&qkvh, g_qkv_hi);
    cudaGetSymbolAddress((void**)&qkvl, g_qkv_lo);
    cudaGetSymbolAddress((void**)&zh, g_z_hi);
    cudaGetSymbolAddress((void**)&zl, g_z_lo);
    cudaGetSymbolAddress((void**)&bpack, g_bpack);

    // 1) pack + split weights, pack bias
    pack_w_kernel<<<(NQKV * D_MODEL + 255) / 256, 256>>>(
        Wq, Wk, Wv, Wo, bq, bk, bv, qh, ql, oh, ol, bpack);

    // 2) split x to bf16 hi/lo
    {
        int n = MROWS * D_MODEL;
        split_kernel<<<(n + 255) / 256, 256>>>(x, xh, xl, n);
    }

    // 3) QKV projection -> bf16 hi/lo qkv
    {
        dim3 grid(NQKV / 128, MROWS / 128);
        mma_gemm_kernel<<<grid, 256, MMA_SMEM>>>(
            xh, xl, qh, ql, bpack, nullptr, qkvh, qkvl, MROWS, NQKV, D_MODEL);
    }

    // 4) causal flash attention (mma) -> z bf16 hi/lo
    {
        dim3 grid(S_LEN / 128, NH, BATCH);
        flash_mma_kernel<<<grid, 256, FS_SMEM>>>(qkvh, qkvl, zh, zl);
    }

    // 5) output projection -> fp32 out
    {
        dim3 grid(D_MODEL / 128, MROWS / 128);
        mma_gemm_kernel<<<grid, 256, MMA_SMEM>>>(
            zh, zl, oh, ol, bo, out, nullptr, nullptr, MROWS, D_MODEL, D_MODEL);
    }
}